// round 3
// baseline (speedup 1.0000x reference)
#include <cuda_runtime.h>
#include <cuda_fp16.h>
#include <stdint.h>

// Problem dims
#define T_STEPS 4
#define B_DIM   64
#define N_DIM   196
#define D_DIM   512
#define C_DIM   1000
#define C_PAD   1024
#define BND     (B_DIM * N_DIM * D_DIM)        // 6,422,528
#define M_ROWS  (T_STEPS * B_DIM * N_DIM)      // 50,176

// GEMM tiling: CTA 128x256, BK=32, 4 stages, 8 warps (2M x 4N), warp tile 64x64
#define BM 128
#define BN 256
#define BK 32
#define NKT (D_DIM / BK)                       // 16
#define ROWB 80                                 // 40 halves per row (pad for ldmatrix)
#define STAGE_A_BYTES (BM * ROWB)               // 10240
#define STAGE_B_BYTES (BN * ROWB)               // 20480
#define STAGE_BYTES   (STAGE_A_BYTES + STAGE_B_BYTES)
#define SMEM_STG0     1024                      // bias in [0, 1024)
#define SMEM_TOTAL    (SMEM_STG0 + 4 * STAGE_BYTES)   // 123904

// Scratch: fp16 spikes [M_ROWS, D] and fp16 W padded [C_PAD, D]
__device__ __align__(256) __half g_spk[(size_t)T_STEPS * BND];
__device__ __align__(256) __half g_wh[(size_t)C_PAD * D_DIM];

static __device__ __forceinline__ uint32_t smem_u32(const void* p) {
    return (uint32_t)__cvta_generic_to_shared(p);
}

#define CP_ASYNC16(dst, src) \
    asm volatile("cp.async.cg.shared.global [%0], [%1], 16;\n" :: "r"(dst), "l"(src))
#define CP_COMMIT() asm volatile("cp.async.commit_group;\n" ::: "memory")
#define CP_WAIT(n)  asm volatile("cp.async.wait_group %0;\n" :: "n"(n) : "memory")

// ---------------------------------------------------------------------------
// LIF scan over T=4: v = v + (x - v)/2; spike = v >= 1; hard reset v = 0.
// Exact fp32 ops, identical rounding to reference. Spikes -> fp16 {0,1}.
// ---------------------------------------------------------------------------
__global__ __launch_bounds__(256) void spike_kernel(const float* __restrict__ x) {
    int base = (blockIdx.x * 256 + threadIdx.x) * 4;
    float v[4] = {0.f, 0.f, 0.f, 0.f};
#pragma unroll
    for (int t = 0; t < 4; t++) {
        float4 xv = *reinterpret_cast<const float4*>(x + (size_t)t * BND + base);
        float xa[4] = {xv.x, xv.y, xv.z, xv.w};
        __half h[4];
#pragma unroll
        for (int j = 0; j < 4; j++) {
            v[j] = v[j] + (xa[j] - v[j]) * 0.5f;
            bool sp = (v[j] >= 1.0f);
            h[j] = sp ? __float2half_rn(1.0f) : __float2half_rn(0.0f);
            if (sp) v[j] = 0.0f;
        }
        uint2 u;
        u.x = ((uint32_t)__half_as_ushort(h[1]) << 16) | __half_as_ushort(h[0]);
        u.y = ((uint32_t)__half_as_ushort(h[3]) << 16) | __half_as_ushort(h[2]);
        *reinterpret_cast<uint2*>(g_spk + (size_t)t * BND + base) = u;
    }
}

// ---------------------------------------------------------------------------
// W [1000, 512] fp32 -> fp16, zero-padded to [1024, 512]
// ---------------------------------------------------------------------------
__global__ __launch_bounds__(256) void wconv_kernel(const float* __restrict__ W) {
    int base = (blockIdx.x * 256 + threadIdx.x) * 4;
    int row = base >> 9;
    uint2 u;
    if (row < C_DIM) {
        float4 w = *reinterpret_cast<const float4*>(W + base);
        __half h0 = __float2half_rn(w.x), h1 = __float2half_rn(w.y);
        __half h2 = __float2half_rn(w.z), h3 = __float2half_rn(w.w);
        u.x = ((uint32_t)__half_as_ushort(h1) << 16) | __half_as_ushort(h0);
        u.y = ((uint32_t)__half_as_ushort(h3) << 16) | __half_as_ushort(h2);
    } else {
        u.x = 0u; u.y = 0u;
    }
    *reinterpret_cast<uint2*>(g_wh + base) = u;
}

// ---------------------------------------------------------------------------
// GEMM: out[m,c] = sum_k spk[m,k]*W[c,k] + b[c]
// mma.sync m16n8k16 f16->f32. One __syncthreads per k-iter, 4-stage cp.async.
// ---------------------------------------------------------------------------
__device__ __forceinline__ void load_stage(uint32_t stg_base, const __half* gA,
                                           const __half* gB, int kt, int tid) {
    // A: 128 rows x 64B = 512 x 16B vectors (2/thread)
#pragma unroll
    for (int i = 0; i < 2; i++) {
        int v = tid + i * 256;
        int row = v >> 2, kv = v & 3;
        CP_ASYNC16(stg_base + row * ROWB + kv * 16,
                   gA + (size_t)row * D_DIM + kt * BK + kv * 8);
    }
    // B: 256 rows x 64B = 1024 x 16B vectors (4/thread)
    uint32_t sb = stg_base + STAGE_A_BYTES;
#pragma unroll
    for (int i = 0; i < 4; i++) {
        int v = tid + i * 256;
        int row = v >> 2, kv = v & 3;
        CP_ASYNC16(sb + row * ROWB + kv * 16,
                   gB + (size_t)row * D_DIM + kt * BK + kv * 8);
    }
    CP_COMMIT();
}

__global__ __launch_bounds__(256, 1) void gemm_kernel(const float* __restrict__ bias,
                                                      float* __restrict__ out) {
    extern __shared__ __align__(1024) char smem[];
    uint32_t smem_base = smem_u32(smem);
    float* sBias = reinterpret_cast<float*>(smem);

    const int tid = threadIdx.x;
    const int wid = tid >> 5;
    const int lane = tid & 31;
    const int bn = blockIdx.x;   // 4 tiles over C_PAD (fast -> shares A in L2)
    const int bm = blockIdx.y;   // 392 tiles over M

    const int wm = wid >> 2;     // 0..1
    const int wn = wid & 3;      // 0..3
    const int mat = lane >> 3;
    const int roff = (lane & 7) + (mat & 1) * 8;
    const int koff = (mat >> 1) * 8;

    {
        int c = bn * BN + tid;
        sBias[tid] = (c < C_DIM) ? bias[c] : 0.f;
    }

    const __half* gA = g_spk + (size_t)bm * BM * D_DIM;
    const __half* gB = g_wh + (size_t)bn * BN * D_DIM;

    float acc[4][8][4];
#pragma unroll
    for (int i = 0; i < 4; i++)
#pragma unroll
        for (int j = 0; j < 8; j++)
#pragma unroll
            for (int k = 0; k < 4; k++) acc[i][j][k] = 0.f;

    // Prologue: stages 0..2 <- k-tiles 0..2 (3 commit groups)
    load_stage(smem_base + SMEM_STG0 + 0 * STAGE_BYTES, gA, gB, 0, tid);
    load_stage(smem_base + SMEM_STG0 + 1 * STAGE_BYTES, gA, gB, 1, tid);
    load_stage(smem_base + SMEM_STG0 + 2 * STAGE_BYTES, gA, gB, 2, tid);

#pragma unroll 1
    for (int kt = 0; kt < NKT; kt++) {
        CP_WAIT(2);         // group kt complete (one group per iter, always commit)
        __syncthreads();    // data ready; all warps done with stage (kt-1)&3

        if (kt + 3 < NKT) {
            load_stage(smem_base + SMEM_STG0 + ((kt + 3) & 3) * STAGE_BYTES,
                       gA, gB, kt + 3, tid);
        } else {
            CP_COMMIT();    // keep group count in lockstep
        }

        uint32_t sa = smem_base + SMEM_STG0 + (kt & 3) * STAGE_BYTES;
        uint32_t sb = sa + STAGE_A_BYTES;

#pragma unroll
        for (int ks = 0; ks < 2; ks++) {     // two k16 steps per BK=32
            uint32_t a[4][4];
#pragma unroll
            for (int mi = 0; mi < 4; mi++) {
                int r = wm * 64 + mi * 16 + roff;
                uint32_t addr = sa + r * ROWB + (ks * 16 + koff) * 2;
                asm volatile("ldmatrix.sync.aligned.m8n8.x4.shared.b16 {%0,%1,%2,%3}, [%4];\n"
                             : "=r"(a[mi][0]), "=r"(a[mi][1]), "=r"(a[mi][2]), "=r"(a[mi][3])
                             : "r"(addr));
            }
            uint32_t bq[8][2];
#pragma unroll
            for (int np = 0; np < 4; np++) {
                int r = wn * 64 + np * 16 + roff;
                uint32_t addr = sb + r * ROWB + (ks * 16 + koff) * 2;
                uint32_t r0, r1, r2, r3;
                asm volatile("ldmatrix.sync.aligned.m8n8.x4.shared.b16 {%0,%1,%2,%3}, [%4];\n"
                             : "=r"(r0), "=r"(r1), "=r"(r2), "=r"(r3)
                             : "r"(addr));
                bq[2 * np][0] = r0; bq[2 * np + 1][0] = r1;
                bq[2 * np][1] = r2; bq[2 * np + 1][1] = r3;
            }
#pragma unroll
            for (int mi = 0; mi < 4; mi++) {
#pragma unroll
                for (int nf = 0; nf < 8; nf++) {
                    asm volatile(
                        "mma.sync.aligned.m16n8k16.row.col.f32.f16.f16.f32 "
                        "{%0,%1,%2,%3}, {%4,%5,%6,%7}, {%8,%9}, {%0,%1,%2,%3};\n"
                        : "+f"(acc[mi][nf][0]), "+f"(acc[mi][nf][1]),
                          "+f"(acc[mi][nf][2]), "+f"(acc[mi][nf][3])
                        : "r"(a[mi][0]), "r"(a[mi][1]), "r"(a[mi][2]), "r"(a[mi][3]),
                          "r"(bq[nf][0]), "r"(bq[nf][1]));
                }
            }
        }
    }

    // Epilogue: +bias, streaming float2 stores (don't evict L2-resident A)
    const int r2 = lane >> 2;
    const int c2 = (lane & 3) * 2;
    const int growb = bm * BM + wm * 64;
    const int lcolb = wn * 64 + c2;
#pragma unroll
    for (int mi = 0; mi < 4; mi++) {
#pragma unroll
        for (int nf = 0; nf < 8; nf++) {
            int lc = lcolb + nf * 8;
            int col = bn * BN + lc;
            if (col < C_DIM) {
                float b0 = sBias[lc], b1 = sBias[lc + 1];
                size_t o0 = (size_t)(growb + mi * 16 + r2) * C_DIM + col;
                float2 v0 = make_float2(acc[mi][nf][0] + b0, acc[mi][nf][1] + b1);
                float2 v1 = make_float2(acc[mi][nf][2] + b0, acc[mi][nf][3] + b1);
                __stcs(reinterpret_cast<float2*>(out + o0), v0);
                __stcs(reinterpret_cast<float2*>(out + o0 + (size_t)8 * C_DIM), v1);
            }
        }
    }
}

// ---------------------------------------------------------------------------
extern "C" void kernel_launch(void* const* d_in, const int* in_sizes, int n_in,
                              void* d_out, int out_size) {
    const float* x = (const float*)d_in[0];   // [4, 64, 196, 512] fp32
    const float* W = (const float*)d_in[1];   // [1000, 512] fp32
    const float* b = (const float*)d_in[2];   // [1000] fp32
    float* out = (float*)d_out;               // [4, 64, 196, 1000] fp32

    cudaFuncSetAttribute(gemm_kernel, cudaFuncAttributeMaxDynamicSharedMemorySize,
                         SMEM_TOTAL);

    spike_kernel<<<BND / 4 / 256, 256>>>(x);
    wconv_kernel<<<(C_PAD * D_DIM) / 4 / 256, 256>>>(W);
    gemm_kernel<<<dim3(C_PAD / BN, M_ROWS / BM), 256, SMEM_TOTAL>>>(b, out);
}